// round 1
// baseline (speedup 1.0000x reference)
#include <cuda_runtime.h>

#define NN 50000
#define EE 800000

typedef unsigned long long ull;

// ---------------- device scratch (static allocations only) ----------------
__device__ float g_q[NN * 64];
__device__ float g_k[NN * 64];
__device__ float g_v[NN * 64];
__device__ float g_skip[NN * 64];
__device__ float g_h[NN * 64];
__device__ int   g_rowptr[NN + 1];
__device__ int   g_cursor[NN];
__device__ int   g_srcs[EE];
__device__ int   g_eids[EE];

// ---------------- packed f32x2 helpers (sm_103a fma.rn.f32x2) -------------
__device__ __forceinline__ ull pk2(float x, float y) {
    ull r; asm("mov.b64 %0, {%1,%2};" : "=l"(r) : "f"(x), "f"(y)); return r;
}
__device__ __forceinline__ ull dup2(float x) { return pk2(x, x); }
__device__ __forceinline__ void up2(ull a, float& x, float& y) {
    asm("mov.b64 {%0,%1}, %2;" : "=f"(x), "=f"(y) : "l"(a));
}
__device__ __forceinline__ ull fma2(ull a, ull b, ull c) {
    ull d; asm("fma.rn.f32x2 %0, %1, %2, %3;" : "=l"(d) : "l"(a), "l"(b), "l"(c)); return d;
}
__device__ __forceinline__ ull add2(ull a, ull b) {
    ull d; asm("add.rn.f32x2 %0, %1, %2;" : "=l"(d) : "l"(a), "l"(b)); return d;
}
__device__ __forceinline__ ull mul2(ull a, ull b) {
    ull d; asm("mul.rn.f32x2 %0, %1, %2;" : "=l"(d) : "l"(a), "l"(b)); return d;
}

// ---------------- CSR build ------------------------------------------------
__global__ void k_zero_rowptr() {
    int i = blockIdx.x * blockDim.x + threadIdx.x;
    if (i <= NN) g_rowptr[i] = 0;
}

__global__ void k_hist(const int* __restrict__ dst) {
    int i = blockIdx.x * blockDim.x + threadIdx.x;
    if (i < EE) atomicAdd(&g_rowptr[dst[i] + 1], 1);
}

// single-block inclusive scan over NN+1 entries; also fills cursors
__global__ void k_scan() {
    __shared__ int sd[1024];
    __shared__ int carry;
    int tid = threadIdx.x;
    if (tid == 0) carry = 0;
    __syncthreads();
    const int n = NN + 1;
    for (int base = 0; base < n; base += 1024) {
        int i = base + tid;
        int v = (i < n) ? g_rowptr[i] : 0;
        sd[tid] = v;
        __syncthreads();
        for (int off = 1; off < 1024; off <<= 1) {
            int t = (tid >= off) ? sd[tid - off] : 0;
            __syncthreads();
            sd[tid] += t;
            __syncthreads();
        }
        int val = sd[tid] + carry;
        if (i < n) {
            g_rowptr[i] = val;
            if (i < NN) g_cursor[i] = val;
        }
        __syncthreads();
        if (tid == 1023) carry = val;
        __syncthreads();
    }
}

__global__ void k_scatter(const int* __restrict__ src, const int* __restrict__ dst) {
    int i = blockIdx.x * blockDim.x + threadIdx.x;
    if (i < EE) {
        int d = dst[i];
        int pos = atomicAdd(&g_cursor[d], 1);
        g_srcs[pos] = src[i];
        g_eids[pos] = i;
    }
}

// ---------------- node GEMM: [N,64] x (Wq|Wk|Wv|Ws) -> q,k,v,skip ----------
// 256 threads: thread j owns output column (j%64) of matrix (j/64).
// Weight column held in registers, 8 nodes per tile staged in smem transposed.
__global__ __launch_bounds__(256, 2) void k_node_gemm(
    const float* __restrict__ xin, int in_is_gh,
    const float* __restrict__ Wq, const float* __restrict__ bq,
    const float* __restrict__ Wk, const float* __restrict__ bk,
    const float* __restrict__ Wv, const float* __restrict__ bv,
    const float* __restrict__ Ws, const float* __restrict__ bs)
{
    __shared__ __align__(16) float xs[64 * 8];  // xs[d*8 + nl]
    const float* x = in_is_gh ? g_h : xin;
    int tid = threadIdx.x;
    int sel = tid >> 6, col = tid & 63;

    const float* W; const float* B; float* O;
    if      (sel == 0) { W = Wq; B = bq; O = g_q; }
    else if (sel == 1) { W = Wk; B = bk; O = g_k; }
    else if (sel == 2) { W = Wv; B = bv; O = g_v; }
    else               { W = Ws; B = bs; O = g_skip; }

    float w[64];
#pragma unroll
    for (int d = 0; d < 64; d++) w[d] = W[d * 64 + col];
    float bias = B[col];

    const int ntiles = NN / 8;  // 6250, exact
    for (int t = blockIdx.x; t < ntiles; t += gridDim.x) {
        int n0 = t * 8;
        __syncthreads();
        // stage 8 nodes transposed: xs[d][nl] = x[(n0+nl)*64 + d]
#pragma unroll
        for (int kk = 0; kk < 2; kk++) {
            int idx = tid + kk * 256;
            int nl = idx >> 6, d = idx & 63;
            xs[d * 8 + nl] = x[(n0 + nl) * 64 + d];
        }
        __syncthreads();

        ull acc2[4];
#pragma unroll
        for (int p = 0; p < 4; p++) acc2[p] = dup2(bias);

#pragma unroll
        for (int d = 0; d < 64; d++) {
            ull wd = dup2(w[d]);
            ulonglong2 xa = *(const ulonglong2*)&xs[d * 8];      // nodes 0..3
            ulonglong2 xb = *(const ulonglong2*)&xs[d * 8 + 4];  // nodes 4..7
            acc2[0] = fma2(xa.x, wd, acc2[0]);
            acc2[1] = fma2(xa.y, wd, acc2[1]);
            acc2[2] = fma2(xb.x, wd, acc2[2]);
            acc2[3] = fma2(xb.y, wd, acc2[3]);
        }
#pragma unroll
        for (int p = 0; p < 4; p++) {
            float a, b; up2(acc2[p], a, b);
            O[(n0 + 2 * p) * 64 + col]     = a;
            O[(n0 + 2 * p + 1) * 64 + col] = b;
        }
    }
}

// ---------------- fused edge aggregation: warp per dst node ----------------
// lane l owns channels (2l, 2l+1). H=2: lanes 0-15 = head0, 16-31 = head1.
// Online softmax over incident edges, e = edge_attr @ We computed in-register.
template <int H>
__global__ __launch_bounds__(256, 2) void k_edge_agg(
    const float* __restrict__ edge_attr,
    const float* __restrict__ We,
    float* __restrict__ out, int out_is_gh,
    const float* __restrict__ prelu, int apply_prelu)
{
    __shared__ __align__(16) float ea_s[8][32];
    int lane = threadIdx.x & 31;
    int wslot = threadIdx.x >> 5;
    int n = blockIdx.x * 8 + wslot;
    if (n >= NN) return;

    float* o = out_is_gh ? g_h : out;

    // We column pair in registers: wreg[d] = (We[d][2l], We[d][2l+1])
    ull wreg[32];
#pragma unroll
    for (int d = 0; d < 32; d++) wreg[d] = *(const ull*)&We[d * 64 + 2 * lane];

    ull q2    = *(const ull*)&g_q[n * 64 + 2 * lane];
    ull skip2 = *(const ull*)&g_skip[n * 64 + 2 * lane];

    ull acc = 0;                 // (0.f, 0.f)
    float m = -3.0e38f, s = 0.f;
    const float scale = (H == 2) ? 0.17677669529663687f  // 1/sqrt(32)
                                 : 0.125f;               // 1/sqrt(64)

    int beg = g_rowptr[n], end = g_rowptr[n + 1];
    for (int i = beg; i < end; i++) {
        int src = g_srcs[i];
        int eid = g_eids[i];

        ea_s[wslot][lane] = edge_attr[eid * 32 + lane];
        __syncwarp();

        ull e2 = 0;
#pragma unroll
        for (int d = 0; d < 32; d += 4) {
            float4 ev = *(const float4*)&ea_s[wslot][d];
            e2 = fma2(dup2(ev.x), wreg[d],     e2);
            e2 = fma2(dup2(ev.y), wreg[d + 1], e2);
            e2 = fma2(dup2(ev.z), wreg[d + 2], e2);
            e2 = fma2(dup2(ev.w), wreg[d + 3], e2);
        }
        __syncwarp();  // all reads of ea_s done before next iteration's store

        ull k2 = *(const ull*)&g_k[src * 64 + 2 * lane];
        ull p2 = mul2(q2, add2(k2, e2));
        float px, py; up2(p2, px, py);
        float pl = px + py;
        // head-wise butterfly reduce
        pl += __shfl_xor_sync(0xffffffffu, pl, 1);
        pl += __shfl_xor_sync(0xffffffffu, pl, 2);
        pl += __shfl_xor_sync(0xffffffffu, pl, 4);
        pl += __shfl_xor_sync(0xffffffffu, pl, 8);
        if (H == 1) pl += __shfl_xor_sync(0xffffffffu, pl, 16);

        float alpha = pl * scale;
        float nm = fmaxf(m, alpha);
        float sc = __expf(m - nm);
        float wgt = __expf(alpha - nm);
        s = s * sc + wgt;
        m = nm;

        ull v2 = *(const ull*)&g_v[src * 64 + 2 * lane];
        ull vpe = add2(v2, e2);
        acc = fma2(acc, dup2(sc), mul2(dup2(wgt), vpe));
    }

    float inv = (s > 0.f) ? 1.f / s : 0.f;
    float ax, ay; up2(acc, ax, ay);
    float sx, sy; up2(skip2, sx, sy);
    float ox = ax * inv + sx;
    float oy = ay * inv + sy;
    if (apply_prelu) {
        float a = *prelu;
        ox = (ox >= 0.f) ? ox : a * ox;
        oy = (oy >= 0.f) ? oy : a * oy;
    }
    *(float2*)&o[n * 64 + 2 * lane] = make_float2(ox, oy);
}

// ---------------- launch ----------------------------------------------------
extern "C" void kernel_launch(void* const* d_in, const int* in_sizes, int n_in,
                              void* d_out, int out_size)
{
    const float* x  = (const float*)d_in[0];
    const float* ea = (const float*)d_in[1];
    const int*   ei = (const int*)d_in[2];
    const int* src = ei;
    const int* dst = ei + EE;

    const float *Wq[3], *bq[3], *Wk[3], *bk[3], *Wv[3], *bv[3], *We[3], *Ws[3], *bs[3];
    for (int l = 0; l < 3; l++) {
        int b = 3 + 9 * l;
        Wq[l] = (const float*)d_in[b + 0];
        bq[l] = (const float*)d_in[b + 1];
        Wk[l] = (const float*)d_in[b + 2];
        bk[l] = (const float*)d_in[b + 3];
        Wv[l] = (const float*)d_in[b + 4];
        bv[l] = (const float*)d_in[b + 5];
        We[l] = (const float*)d_in[b + 6];
        Ws[l] = (const float*)d_in[b + 7];
        bs[l] = (const float*)d_in[b + 8];
    }
    const float* prelu = (const float*)d_in[30];
    float* out = (float*)d_out;

    // CSR build (once per launch; reused by all 3 layers)
    k_zero_rowptr<<<(NN + 256) / 256, 256>>>();
    k_hist<<<(EE + 255) / 256, 256>>>(dst);
    k_scan<<<1, 1024>>>();
    k_scatter<<<(EE + 255) / 256, 256>>>(src, dst);

    const int EDGE_BLOCKS = NN / 8;  // 6250, warp per node

    // layer 0 (H=2, prelu)
    k_node_gemm<<<592, 256>>>(x, 0, Wq[0], bq[0], Wk[0], bk[0], Wv[0], bv[0], Ws[0], bs[0]);
    k_edge_agg<2><<<EDGE_BLOCKS, 256>>>(ea, We[0], nullptr, 1, prelu, 1);

    // layer 1 (H=2, prelu)
    k_node_gemm<<<592, 256>>>(nullptr, 1, Wq[1], bq[1], Wk[1], bk[1], Wv[1], bv[1], Ws[1], bs[1]);
    k_edge_agg<2><<<EDGE_BLOCKS, 256>>>(ea, We[1], nullptr, 1, prelu, 1);

    // layer 2 (H=1, no prelu, write d_out)
    k_node_gemm<<<592, 256>>>(nullptr, 1, Wq[2], bq[2], Wk[2], bk[2], Wv[2], bv[2], Ws[2], bs[2]);
    k_edge_agg<1><<<EDGE_BLOCKS, 256>>>(ea, We[2], out, 0, prelu, 0);
}

// round 2
// speedup vs baseline: 1.7087x; 1.7087x over previous
#include <cuda_runtime.h>

#define NN 50000
#define EE 800000

typedef unsigned long long ull;

// ---------------- device scratch (static allocations only) ----------------
__device__ float g_q[NN * 64];
__device__ float g_k[NN * 64];
__device__ float g_v[NN * 64];
__device__ float g_skip[NN * 64];
__device__ float g_u[NN * 64];
__device__ float g_h[NN * 64];
__device__ float g_ea[EE * 32];      // edge_attr permuted into CSR order
__device__ float g_M[64 * 64];       // folded Wq*We for u
__device__ float g_bu[64];
__device__ int   g_rowptr[NN + 1];
__device__ int   g_cursor[NN];
__device__ int   g_srcs[EE];
__device__ int   g_eids[EE];

// ---------------- packed f32x2 helpers (sm_103a fma.rn.f32x2) -------------
__device__ __forceinline__ ull pk2(float x, float y) {
    ull r; asm("mov.b64 %0, {%1,%2};" : "=l"(r) : "f"(x), "f"(y)); return r;
}
__device__ __forceinline__ ull dup2(float x) { return pk2(x, x); }
__device__ __forceinline__ void up2(ull a, float& x, float& y) {
    asm("mov.b64 {%0,%1}, %2;" : "=f"(x), "=f"(y) : "l"(a));
}
__device__ __forceinline__ ull fma2(ull a, ull b, ull c) {
    ull d; asm("fma.rn.f32x2 %0, %1, %2, %3;" : "=l"(d) : "l"(a), "l"(b), "l"(c)); return d;
}
__device__ __forceinline__ ull add2(ull a, ull b) {
    ull d; asm("add.rn.f32x2 %0, %1, %2;" : "=l"(d) : "l"(a), "l"(b)); return d;
}
__device__ __forceinline__ ull mul2(ull a, ull b) {
    ull d; asm("mul.rn.f32x2 %0, %1, %2;" : "=l"(d) : "l"(a), "l"(b)); return d;
}

// ---------------- CSR build ------------------------------------------------
__global__ void k_zero_rowptr() {
    int i = blockIdx.x * blockDim.x + threadIdx.x;
    if (i <= NN) g_rowptr[i] = 0;
}

__global__ void k_hist(const int* __restrict__ dst) {
    int i = blockIdx.x * blockDim.x + threadIdx.x;
    if (i < EE) atomicAdd(&g_rowptr[dst[i] + 1], 1);
}

// single-block inclusive scan over NN+1 entries; also fills cursors
__global__ void k_scan() {
    __shared__ int sd[1024];
    __shared__ int carry;
    int tid = threadIdx.x;
    if (tid == 0) carry = 0;
    __syncthreads();
    const int n = NN + 1;
    for (int base = 0; base < n; base += 1024) {
        int i = base + tid;
        int v = (i < n) ? g_rowptr[i] : 0;
        sd[tid] = v;
        __syncthreads();
        for (int off = 1; off < 1024; off <<= 1) {
            int t = (tid >= off) ? sd[tid - off] : 0;
            __syncthreads();
            sd[tid] += t;
            __syncthreads();
        }
        int val = sd[tid] + carry;
        if (i < n) {
            g_rowptr[i] = val;
            if (i < NN) g_cursor[i] = val;
        }
        __syncthreads();
        if (tid == 1023) carry = val;
        __syncthreads();
    }
}

__global__ void k_scatter(const int* __restrict__ src, const int* __restrict__ dst) {
    int i = blockIdx.x * blockDim.x + threadIdx.x;
    if (i < EE) {
        int d = dst[i];
        int pos = atomicAdd(&g_cursor[d], 1);
        g_srcs[pos] = src[i];
        g_eids[pos] = i;
    }
}

// permute edge_attr into CSR order: gather (line-granular) -> coalesced write
__global__ void k_permute_ea(const float* __restrict__ ea) {
    int idx = blockIdx.x * blockDim.x + threadIdx.x;  // over EE*8 float4s
    if (idx < EE * 8) {
        int row = idx >> 3, c4 = idx & 7;
        int e = g_eids[row];
        float4 v = ((const float4*)ea)[(long)e * 8 + c4];
        ((float4*)g_ea)[idx] = v;
    }
}

// ---------------- fold: M = per-head Wq . We  (for u = x@M + bu) ----------
// H=2: M[i, h*32+d] = sum_c Wq[i,h*32+c] * We[d, h*32+c]
// H=1: M[i, j]      = 0.5 * sum_{c<64} Wq[i,c] * We[j&31, c]   (duplicated halves)
__global__ void k_fold(const float* __restrict__ Wq, const float* __restrict__ bq,
                       const float* __restrict__ We, int H) {
    int idx = blockIdx.x * 256 + threadIdx.x;
    if (idx < 4096) {
        int i = idx >> 6, j = idx & 63;
        float s = 0.f;
        if (H == 2) {
            int h = j >> 5, d = j & 31;
            for (int c = 0; c < 32; c++)
                s += Wq[i * 64 + h * 32 + c] * We[d * 64 + h * 32 + c];
        } else {
            int d = j & 31;
            for (int c = 0; c < 64; c++)
                s += Wq[i * 64 + c] * We[d * 64 + c];
            s *= 0.5f;
        }
        g_M[idx] = s;
    }
    if (idx < 64) {
        int j = idx;
        float s = 0.f;
        if (H == 2) {
            int h = j >> 5, d = j & 31;
            for (int c = 0; c < 32; c++)
                s += bq[h * 32 + c] * We[d * 64 + h * 32 + c];
        } else {
            int d = j & 31;
            for (int c = 0; c < 64; c++)
                s += bq[c] * We[d * 64 + c];
            s *= 0.5f;
        }
        g_bu[j] = s;
    }
}

// ---------------- node GEMM: [N,64] x (Wq|Wk|Wv|Ws|M) -> q,k,v,skip,u ------
__global__ __launch_bounds__(320, 2) void k_node_gemm5(
    const float* __restrict__ xin, int in_is_gh,
    const float* __restrict__ Wq, const float* __restrict__ bq,
    const float* __restrict__ Wk, const float* __restrict__ bk,
    const float* __restrict__ Wv, const float* __restrict__ bv,
    const float* __restrict__ Ws, const float* __restrict__ bs)
{
    __shared__ __align__(16) float xs[64 * 8];  // xs[d*8 + nl]
    const float* x = in_is_gh ? g_h : xin;
    int tid = threadIdx.x;
    int sel = tid >> 6, col = tid & 63;

    const float* W; const float* B; float* O;
    if      (sel == 0) { W = Wq;  B = bq;   O = g_q; }
    else if (sel == 1) { W = Wk;  B = bk;   O = g_k; }
    else if (sel == 2) { W = Wv;  B = bv;   O = g_v; }
    else if (sel == 3) { W = Ws;  B = bs;   O = g_skip; }
    else               { W = g_M; B = g_bu; O = g_u; }

    float w[64];
#pragma unroll
    for (int d = 0; d < 64; d++) w[d] = W[d * 64 + col];
    float bias = B[col];

    const int ntiles = NN / 8;  // 6250, exact
    for (int t = blockIdx.x; t < ntiles; t += gridDim.x) {
        int n0 = t * 8;
        __syncthreads();
        for (int idx = tid; idx < 512; idx += 320) {
            int nl = idx >> 6, d = idx & 63;
            xs[d * 8 + nl] = x[(n0 + nl) * 64 + d];
        }
        __syncthreads();

        ull acc2[4];
#pragma unroll
        for (int p = 0; p < 4; p++) acc2[p] = dup2(bias);

#pragma unroll
        for (int d = 0; d < 64; d++) {
            ull wd = dup2(w[d]);
            ulonglong2 xa = *(const ulonglong2*)&xs[d * 8];
            ulonglong2 xb = *(const ulonglong2*)&xs[d * 8 + 4];
            acc2[0] = fma2(xa.x, wd, acc2[0]);
            acc2[1] = fma2(xa.y, wd, acc2[1]);
            acc2[2] = fma2(xb.x, wd, acc2[2]);
            acc2[3] = fma2(xb.y, wd, acc2[3]);
        }
#pragma unroll
        for (int p = 0; p < 4; p++) {
            float a, b; up2(acc2[p], a, b);
            O[(n0 + 2 * p) * 64 + col]     = a;
            O[(n0 + 2 * p + 1) * 64 + col] = b;
        }
    }
}

// ---------------- fused edge aggregation: warp per dst node ----------------
// lane l owns channels (2l, 2l+1). H=2: lanes 0-15 = head0, 16-31 = head1.
// alpha = (q.k + ea.u) * scale ; value = sum(a*v) + (sum(a*ea)) @ We
template <int H>
__global__ __launch_bounds__(256) void k_edge_agg(
    const float* __restrict__ We,
    float* __restrict__ out, int out_is_gh,
    const float* __restrict__ prelu, int apply_prelu)
{
    __shared__ __align__(16) float we_s[32 * 64];  // We staged (epilogue)
    __shared__ __align__(16) float zs[8][64];

    int tid = threadIdx.x;
    int lane = tid & 31;
    int wslot = tid >> 5;
    int n = blockIdx.x * 8 + wslot;  // grid is exactly NN/8

    for (int idx = tid; idx < 2048; idx += 256) we_s[idx] = We[idx];
    __syncthreads();

    float* o = out_is_gh ? g_h : out;

    ull q2    = *(const ull*)&g_q[n * 64 + 2 * lane];
    ull u2    = *(const ull*)&g_u[n * 64 + 2 * lane];
    ull skip2 = *(const ull*)&g_skip[n * 64 + 2 * lane];

    ull accv = 0, accz = 0;
    float m = -3.0e38f, s = 0.f;
    const float scale = (H == 2) ? 0.17677669529663687f : 0.125f;
    const int eaoff = (2 * lane) & 31;

    int beg = g_rowptr[n], end = g_rowptr[n + 1];

    ull k2n = 0, v2n = 0, e2n = 0;
    if (beg < end) {
        int s0 = g_srcs[beg];
        k2n = *(const ull*)&g_k[s0 * 64 + 2 * lane];
        v2n = *(const ull*)&g_v[s0 * 64 + 2 * lane];
        e2n = *(const ull*)&g_ea[beg * 32 + eaoff];
    }

    for (int i = beg; i < end; i++) {
        ull k2 = k2n, v2 = v2n, e2 = e2n;
        if (i + 1 < end) {
            int s1 = g_srcs[i + 1];
            k2n = *(const ull*)&g_k[s1 * 64 + 2 * lane];
            v2n = *(const ull*)&g_v[s1 * 64 + 2 * lane];
            e2n = *(const ull*)&g_ea[(i + 1) * 32 + eaoff];
        }

        ull pt = add2(mul2(q2, k2), mul2(u2, e2));
        float px, py; up2(pt, px, py);
        float pl = px + py;
        pl += __shfl_xor_sync(0xffffffffu, pl, 1);
        pl += __shfl_xor_sync(0xffffffffu, pl, 2);
        pl += __shfl_xor_sync(0xffffffffu, pl, 4);
        pl += __shfl_xor_sync(0xffffffffu, pl, 8);
        if (H == 1) pl += __shfl_xor_sync(0xffffffffu, pl, 16);

        float alpha = pl * scale;
        float nm = fmaxf(m, alpha);
        float sc = __expf(m - nm);
        float wgt = __expf(alpha - nm);
        s = s * sc + wgt;
        m = nm;

        ull sc2 = dup2(sc), w2 = dup2(wgt);
        accv = fma2(accv, sc2, mul2(w2, v2));
        accz = fma2(accz, sc2, mul2(w2, e2));
    }

    // z @ We per node (epilogue)
    float zx, zy; up2(accz, zx, zy);
    zs[wslot][2 * lane] = zx;
    zs[wslot][2 * lane + 1] = zy;
    __syncwarp();

    ull ze = 0;
    int base = (H == 2) ? ((lane >> 4) * 32) : 0;
#pragma unroll
    for (int d = 0; d < 32; d++) {
        ull wp = *(const ull*)&we_s[d * 64 + 2 * lane];
        ze = fma2(dup2(zs[wslot][base + d]), wp, ze);
    }

    float inv = (s > 0.f) ? 1.f / s : 0.f;
    float ax, ay; up2(accv, ax, ay);
    float ex, ey; up2(ze, ex, ey);
    float sx, sy; up2(skip2, sx, sy);
    float ox = (ax + ex) * inv + sx;
    float oy = (ay + ey) * inv + sy;
    if (apply_prelu) {
        float a = *prelu;
        ox = (ox >= 0.f) ? ox : a * ox;
        oy = (oy >= 0.f) ? oy : a * oy;
    }
    *(float2*)&o[n * 64 + 2 * lane] = make_float2(ox, oy);
}

// ---------------- launch ----------------------------------------------------
extern "C" void kernel_launch(void* const* d_in, const int* in_sizes, int n_in,
                              void* d_out, int out_size)
{
    const float* x  = (const float*)d_in[0];
    const float* ea = (const float*)d_in[1];
    const int*   ei = (const int*)d_in[2];
    const int* src = ei;
    const int* dst = ei + EE;

    const float *Wq[3], *bq[3], *Wk[3], *bk[3], *Wv[3], *bv[3], *We[3], *Ws[3], *bs[3];
    for (int l = 0; l < 3; l++) {
        int b = 3 + 9 * l;
        Wq[l] = (const float*)d_in[b + 0];
        bq[l] = (const float*)d_in[b + 1];
        Wk[l] = (const float*)d_in[b + 2];
        bk[l] = (const float*)d_in[b + 3];
        Wv[l] = (const float*)d_in[b + 4];
        bv[l] = (const float*)d_in[b + 5];
        We[l] = (const float*)d_in[b + 6];
        Ws[l] = (const float*)d_in[b + 7];
        bs[l] = (const float*)d_in[b + 8];
    }
    const float* prelu = (const float*)d_in[30];
    float* out = (float*)d_out;

    // CSR build (once per launch; reused by all 3 layers)
    k_zero_rowptr<<<(NN + 256) / 256, 256>>>();
    k_hist<<<(EE + 255) / 256, 256>>>(dst);
    k_scan<<<1, 1024>>>();
    k_scatter<<<(EE + 255) / 256, 256>>>(src, dst);
    k_permute_ea<<<(EE * 8 + 255) / 256, 256>>>(ea);

    const int EDGE_BLOCKS = NN / 8;  // 6250

    // layer 0 (H=2, prelu)
    k_fold<<<16, 256>>>(Wq[0], bq[0], We[0], 2);
    k_node_gemm5<<<592, 320>>>(x, 0, Wq[0], bq[0], Wk[0], bk[0], Wv[0], bv[0], Ws[0], bs[0]);
    k_edge_agg<2><<<EDGE_BLOCKS, 256>>>(We[0], nullptr, 1, prelu, 1);

    // layer 1 (H=2, prelu)
    k_fold<<<16, 256>>>(Wq[1], bq[1], We[1], 2);
    k_node_gemm5<<<592, 320>>>(nullptr, 1, Wq[1], bq[1], Wk[1], bk[1], Wv[1], bv[1], Ws[1], bs[1]);
    k_edge_agg<2><<<EDGE_BLOCKS, 256>>>(We[1], nullptr, 1, prelu, 1);

    // layer 2 (H=1, no prelu, write d_out)
    k_fold<<<16, 256>>>(Wq[2], bq[2], We[2], 1);
    k_node_gemm5<<<592, 320>>>(nullptr, 1, Wq[2], bq[2], Wk[2], bk[2], Wv[2], bv[2], Ws[2], bs[2]);
    k_edge_agg<1><<<EDGE_BLOCKS, 256>>>(We[2], out, 0, prelu, 0);
}

// round 3
// speedup vs baseline: 2.3181x; 1.3567x over previous
#include <cuda_runtime.h>

#define NN 50000
#define EE 800000

typedef unsigned long long ull;

// ---------------- device scratch (static allocations only) ----------------
__device__ float g_q[NN * 64];
__device__ float g_k[NN * 64];
__device__ float g_v[NN * 64];
__device__ float g_skip[NN * 64];
__device__ float g_u[NN * 64];
__device__ float g_h[NN * 64];
__device__ float g_ea[EE * 32];      // edge_attr permuted into CSR order
__device__ float g_M[64 * 64];       // folded Wq*We for u
__device__ float g_bu[64];
__device__ int   g_rowptr[NN + 1];
__device__ int   g_cursor[NN];
__device__ int   g_srcs[EE];
__device__ int   g_eids[EE];
__device__ int   g_part[128];

// ---------------- packed f32x2 helpers (sm_103a fma.rn.f32x2) -------------
__device__ __forceinline__ ull pk2(float x, float y) {
    ull r; asm("mov.b64 %0, {%1,%2};" : "=l"(r) : "f"(x), "f"(y)); return r;
}
__device__ __forceinline__ ull dup2(float x) { return pk2(x, x); }
__device__ __forceinline__ void up2(ull a, float& x, float& y) {
    asm("mov.b64 {%0,%1}, %2;" : "=f"(x), "=f"(y) : "l"(a));
}
__device__ __forceinline__ ull fma2(ull a, ull b, ull c) {
    ull d; asm("fma.rn.f32x2 %0, %1, %2, %3;" : "=l"(d) : "l"(a), "l"(b), "l"(c)); return d;
}
__device__ __forceinline__ ull add2(ull a, ull b) {
    ull d; asm("add.rn.f32x2 %0, %1, %2;" : "=l"(d) : "l"(a), "l"(b)); return d;
}
__device__ __forceinline__ ull mul2(ull a, ull b) {
    ull d; asm("mul.rn.f32x2 %0, %1, %2;" : "=l"(d) : "l"(a), "l"(b)); return d;
}

// ---------------- CSR build ------------------------------------------------
__global__ void k_zero_rowptr() {
    int i = blockIdx.x * blockDim.x + threadIdx.x;
    if (i <= NN) g_rowptr[i] = 0;
}

__global__ void k_hist(const int* __restrict__ dst) {
    int i = blockIdx.x * blockDim.x + threadIdx.x;
    if (i < EE) atomicAdd(&g_rowptr[dst[i] + 1], 1);
}

// two-level scan: A) per-block inclusive scan of 512 elems + partial sums
__global__ void k_scanA() {
    __shared__ int sd[512];
    int b = blockIdx.x, t = threadIdx.x;
    int idx = b * 512 + t;
    int v = (idx <= NN) ? g_rowptr[idx] : 0;
    sd[t] = v;
    __syncthreads();
#pragma unroll
    for (int off = 1; off < 512; off <<= 1) {
        int tv = (t >= off) ? sd[t - off] : 0;
        __syncthreads();
        sd[t] += tv;
        __syncthreads();
    }
    if (idx <= NN) g_rowptr[idx] = sd[t];
    if (t == 511) g_part[b] = sd[511];
}

// C) each block re-scans the 98 partials in smem, adds exclusive offset,
//    also fills cursors
__global__ void k_scanC(int nb) {
    __shared__ int sp[128];
    int b = blockIdx.x, t = threadIdx.x;
    if (t < 128) sp[t] = (t < nb) ? g_part[t] : 0;
    __syncthreads();
#pragma unroll
    for (int off = 1; off < 128; off <<= 1) {
        int tv = (t < 128 && t >= off) ? sp[t - off] : 0;
        __syncthreads();
        if (t < 128) sp[t] += tv;
        __syncthreads();
    }
    int excl = (b == 0) ? 0 : sp[b - 1];
    int idx = b * 512 + t;
    if (idx <= NN) {
        int val = g_rowptr[idx] + excl;
        g_rowptr[idx] = val;
        if (idx < NN) g_cursor[idx] = val;
    }
}

__global__ void k_scatter(const int* __restrict__ src, const int* __restrict__ dst) {
    int i = blockIdx.x * blockDim.x + threadIdx.x;
    if (i < EE) {
        int d = dst[i];
        int pos = atomicAdd(&g_cursor[d], 1);
        g_srcs[pos] = src[i];
        g_eids[pos] = i;
    }
}

// permute edge_attr into CSR order: gather (line-granular) -> coalesced write
__global__ void k_permute_ea(const float* __restrict__ ea) {
    int idx = blockIdx.x * blockDim.x + threadIdx.x;  // over EE*8 float4s
    if (idx < EE * 8) {
        int row = idx >> 3, c4 = idx & 7;
        int e = g_eids[row];
        float4 v = ((const float4*)ea)[(long)e * 8 + c4];
        ((float4*)g_ea)[idx] = v;
    }
}

// ---------------- fold: M = per-head Wq . We  (for u = x@M + bu) ----------
__global__ void k_fold(const float* __restrict__ Wq, const float* __restrict__ bq,
                       const float* __restrict__ We, int H) {
    int idx = blockIdx.x * 256 + threadIdx.x;
    if (idx < 4096) {
        int i = idx >> 6, j = idx & 63;
        float s = 0.f;
        if (H == 2) {
            int h = j >> 5, d = j & 31;
            for (int c = 0; c < 32; c++)
                s += Wq[i * 64 + h * 32 + c] * We[d * 64 + h * 32 + c];
        } else {
            int d = j & 31;
            for (int c = 0; c < 64; c++)
                s += Wq[i * 64 + c] * We[d * 64 + c];
            s *= 0.5f;
        }
        g_M[idx] = s;
    }
    if (idx < 64) {
        int j = idx;
        float s = 0.f;
        if (H == 2) {
            int h = j >> 5, d = j & 31;
            for (int c = 0; c < 32; c++)
                s += bq[h * 32 + c] * We[d * 64 + h * 32 + c];
        } else {
            int d = j & 31;
            for (int c = 0; c < 64; c++)
                s += bq[c] * We[d * 64 + c];
            s *= 0.5f;
        }
        g_bu[j] = s;
    }
}

// ---------------- node GEMM: [N,64] x (Wq|Wk|Wv|Ws|M) -> q,k,v,skip,u ------
__global__ __launch_bounds__(320, 2) void k_node_gemm5(
    const float* __restrict__ xin, int in_is_gh,
    const float* __restrict__ Wq, const float* __restrict__ bq,
    const float* __restrict__ Wk, const float* __restrict__ bk,
    const float* __restrict__ Wv, const float* __restrict__ bv,
    const float* __restrict__ Ws, const float* __restrict__ bs)
{
    __shared__ __align__(16) float xs[64 * 8];  // xs[d*8 + nl]
    const float* x = in_is_gh ? g_h : xin;
    int tid = threadIdx.x;
    int sel = tid >> 6, col = tid & 63;

    const float* W; const float* B; float* O;
    if      (sel == 0) { W = Wq;  B = bq;   O = g_q; }
    else if (sel == 1) { W = Wk;  B = bk;   O = g_k; }
    else if (sel == 2) { W = Wv;  B = bv;   O = g_v; }
    else if (sel == 3) { W = Ws;  B = bs;   O = g_skip; }
    else               { W = g_M; B = g_bu; O = g_u; }

    float w[64];
#pragma unroll
    for (int d = 0; d < 64; d++) w[d] = W[d * 64 + col];
    float bias = B[col];

    const int ntiles = NN / 8;  // 6250, exact
    for (int t = blockIdx.x; t < ntiles; t += gridDim.x) {
        int n0 = t * 8;
        __syncthreads();
        for (int idx = tid; idx < 512; idx += 320) {
            int nl = idx >> 6, d = idx & 63;
            xs[d * 8 + nl] = x[(n0 + nl) * 64 + d];
        }
        __syncthreads();

        ull acc2[4];
#pragma unroll
        for (int p = 0; p < 4; p++) acc2[p] = dup2(bias);

#pragma unroll
        for (int d = 0; d < 64; d++) {
            ull wd = dup2(w[d]);
            ulonglong2 xa = *(const ulonglong2*)&xs[d * 8];
            ulonglong2 xb = *(const ulonglong2*)&xs[d * 8 + 4];
            acc2[0] = fma2(xa.x, wd, acc2[0]);
            acc2[1] = fma2(xa.y, wd, acc2[1]);
            acc2[2] = fma2(xb.x, wd, acc2[2]);
            acc2[3] = fma2(xb.y, wd, acc2[3]);
        }
#pragma unroll
        for (int p = 0; p < 4; p++) {
            float a, b; up2(acc2[p], a, b);
            O[(n0 + 2 * p) * 64 + col]     = a;
            O[(n0 + 2 * p + 1) * 64 + col] = b;
        }
    }
}

// ---------------- fused edge aggregation: warp per dst node ----------------
// lane l owns channels (2l, 2l+1). H=2: lanes 0-15 = head0, 16-31 = head1.
// alpha = (q.k + ea.u) * scale ; value = sum(a*v) + (sum(a*ea)) @ We
// 2 edges per iteration: independent shfl chains, amortized softmax rescale.
template <int H>
__global__ __launch_bounds__(256, 4) void k_edge_agg(
    const float* __restrict__ We,
    float* __restrict__ out, int out_is_gh,
    const float* __restrict__ prelu, int apply_prelu)
{
    __shared__ __align__(16) float we_s[32 * 64];  // We staged (epilogue)
    __shared__ __align__(16) float zs[8][64];

    int tid = threadIdx.x;
    int lane = tid & 31;
    int wslot = tid >> 5;
    int n = blockIdx.x * 8 + wslot;  // grid is exactly NN/8

    for (int idx = tid; idx < 2048; idx += 256) we_s[idx] = We[idx];
    __syncthreads();

    float* o = out_is_gh ? g_h : out;

    ull q2    = *(const ull*)&g_q[n * 64 + 2 * lane];
    ull u2    = *(const ull*)&g_u[n * 64 + 2 * lane];
    ull skip2 = *(const ull*)&g_skip[n * 64 + 2 * lane];

    ull accv = 0, accz = 0;
    float m = -3.0e38f, s = 0.f;
    const float scale = (H == 2) ? 0.17677669529663687f : 0.125f;
    const int eaoff = (2 * lane) & 31;
    const int ch = 2 * lane;

    int beg = g_rowptr[n], end = g_rowptr[n + 1];
    int deg = end - beg;
    int npair = deg >> 1;
    int odd = deg & 1;

    ull k0 = 0, v0 = 0, e0 = 0, k1 = 0, v1 = 0, e1 = 0;

    if (npair > 0) {
        int s0 = g_srcs[beg],     s1 = g_srcs[beg + 1];
        k0 = *(const ull*)&g_k[s0 * 64 + ch];
        k1 = *(const ull*)&g_k[s1 * 64 + ch];
        v0 = *(const ull*)&g_v[s0 * 64 + ch];
        v1 = *(const ull*)&g_v[s1 * 64 + ch];
        e0 = *(const ull*)&g_ea[beg * 32 + eaoff];
        e1 = *(const ull*)&g_ea[(beg + 1) * 32 + eaoff];
    } else if (odd) {
        int s0 = g_srcs[beg];
        k0 = *(const ull*)&g_k[s0 * 64 + ch];
        v0 = *(const ull*)&g_v[s0 * 64 + ch];
        e0 = *(const ull*)&g_ea[beg * 32 + eaoff];
    }

    int i = beg;
    for (int p = 0; p < npair; p++) {
        ull ka = k0, va = v0, ea0 = e0;
        ull kb = k1, vb = v1, eb = e1;
        int j = i + 2;
        // prefetch next pair (or the odd tail edge)
        if (p + 1 < npair) {
            int s0 = g_srcs[j], s1 = g_srcs[j + 1];
            k0 = *(const ull*)&g_k[s0 * 64 + ch];
            k1 = *(const ull*)&g_k[s1 * 64 + ch];
            v0 = *(const ull*)&g_v[s0 * 64 + ch];
            v1 = *(const ull*)&g_v[s1 * 64 + ch];
            e0 = *(const ull*)&g_ea[j * 32 + eaoff];
            e1 = *(const ull*)&g_ea[(j + 1) * 32 + eaoff];
        } else if (odd) {
            int s0 = g_srcs[j];
            k0 = *(const ull*)&g_k[s0 * 64 + ch];
            v0 = *(const ull*)&g_v[s0 * 64 + ch];
            e0 = *(const ull*)&g_ea[j * 32 + eaoff];
        }

        ull pa = add2(mul2(q2, ka), mul2(u2, ea0));
        ull pb = add2(mul2(q2, kb), mul2(u2, eb));
        float ax0, ay0, bx0, by0;
        up2(pa, ax0, ay0);
        up2(pb, bx0, by0);
        float pla = ax0 + ay0;
        float plb = bx0 + by0;
        pla += __shfl_xor_sync(0xffffffffu, pla, 1);
        plb += __shfl_xor_sync(0xffffffffu, plb, 1);
        pla += __shfl_xor_sync(0xffffffffu, pla, 2);
        plb += __shfl_xor_sync(0xffffffffu, plb, 2);
        pla += __shfl_xor_sync(0xffffffffu, pla, 4);
        plb += __shfl_xor_sync(0xffffffffu, plb, 4);
        pla += __shfl_xor_sync(0xffffffffu, pla, 8);
        plb += __shfl_xor_sync(0xffffffffu, plb, 8);
        if (H == 1) {
            pla += __shfl_xor_sync(0xffffffffu, pla, 16);
            plb += __shfl_xor_sync(0xffffffffu, plb, 16);
        }

        float a0 = pla * scale;
        float a1 = plb * scale;
        float nm = fmaxf(m, fmaxf(a0, a1));
        float sc = __expf(m - nm);
        float w0 = __expf(a0 - nm);
        float w1 = __expf(a1 - nm);
        s = s * sc + w0 + w1;
        m = nm;

        ull sc2 = dup2(sc), w02 = dup2(w0), w12 = dup2(w1);
        accv = fma2(accv, sc2, fma2(w02, va, mul2(w12, vb)));
        accz = fma2(accz, sc2, fma2(w02, ea0, mul2(w12, eb)));
        i = j;
    }

    if (odd) {
        ull pa = add2(mul2(q2, k0), mul2(u2, e0));
        float ax0, ay0; up2(pa, ax0, ay0);
        float pla = ax0 + ay0;
        pla += __shfl_xor_sync(0xffffffffu, pla, 1);
        pla += __shfl_xor_sync(0xffffffffu, pla, 2);
        pla += __shfl_xor_sync(0xffffffffu, pla, 4);
        pla += __shfl_xor_sync(0xffffffffu, pla, 8);
        if (H == 1) pla += __shfl_xor_sync(0xffffffffu, pla, 16);
        float a0 = pla * scale;
        float nm = fmaxf(m, a0);
        float sc = __expf(m - nm);
        float w0 = __expf(a0 - nm);
        s = s * sc + w0;
        m = nm;
        ull sc2 = dup2(sc), w02 = dup2(w0);
        accv = fma2(accv, sc2, mul2(w02, v0));
        accz = fma2(accz, sc2, mul2(w02, e0));
    }

    // z @ We per node (epilogue)
    float zx, zy; up2(accz, zx, zy);
    zs[wslot][2 * lane] = zx;
    zs[wslot][2 * lane + 1] = zy;
    __syncwarp();

    ull ze = 0;
    int base = (H == 2) ? ((lane >> 4) * 32) : 0;
#pragma unroll
    for (int d = 0; d < 32; d++) {
        ull wp = *(const ull*)&we_s[d * 64 + 2 * lane];
        ze = fma2(dup2(zs[wslot][base + d]), wp, ze);
    }

    float inv = (s > 0.f) ? 1.f / s : 0.f;
    float avx, avy; up2(accv, avx, avy);
    float ex, ey; up2(ze, ex, ey);
    float sx, sy; up2(skip2, sx, sy);
    float ox = (avx + ex) * inv + sx;
    float oy = (avy + ey) * inv + sy;
    if (apply_prelu) {
        float a = *prelu;
        ox = (ox >= 0.f) ? ox : a * ox;
        oy = (oy >= 0.f) ? oy : a * oy;
    }
    *(float2*)&o[n * 64 + 2 * lane] = make_float2(ox, oy);
}

// ---------------- launch ----------------------------------------------------
extern "C" void kernel_launch(void* const* d_in, const int* in_sizes, int n_in,
                              void* d_out, int out_size)
{
    const float* x  = (const float*)d_in[0];
    const float* ea = (const float*)d_in[1];
    const int*   ei = (const int*)d_in[2];
    const int* src = ei;
    const int* dst = ei + EE;

    const float *Wq[3], *bq[3], *Wk[3], *bk[3], *Wv[3], *bv[3], *We[3], *Ws[3], *bs[3];
    for (int l = 0; l < 3; l++) {
        int b = 3 + 9 * l;
        Wq[l] = (const float*)d_in[b + 0];
        bq[l] = (const float*)d_in[b + 1];
        Wk[l] = (const float*)d_in[b + 2];
        bk[l] = (const float*)d_in[b + 3];
        Wv[l] = (const float*)d_in[b + 4];
        bv[l] = (const float*)d_in[b + 5];
        We[l] = (const float*)d_in[b + 6];
        Ws[l] = (const float*)d_in[b + 7];
        bs[l] = (const float*)d_in[b + 8];
    }
    const float* prelu = (const float*)d_in[30];
    float* out = (float*)d_out;

    const int NB = (NN + 1 + 511) / 512;  // 98

    // CSR build (once per launch; reused by all 3 layers)
    k_zero_rowptr<<<(NN + 256) / 256, 256>>>();
    k_hist<<<(EE + 255) / 256, 256>>>(dst);
    k_scanA<<<NB, 512>>>();
    k_scanC<<<NB, 512>>>(NB);
    k_scatter<<<(EE + 255) / 256, 256>>>(src, dst);
    k_permute_ea<<<(EE * 8 + 255) / 256, 256>>>(ea);

    const int EDGE_BLOCKS = NN / 8;  // 6250

    // layer 0 (H=2, prelu)
    k_fold<<<16, 256>>>(Wq[0], bq[0], We[0], 2);
    k_node_gemm5<<<592, 320>>>(x, 0, Wq[0], bq[0], Wk[0], bk[0], Wv[0], bv[0], Ws[0], bs[0]);
    k_edge_agg<2><<<EDGE_BLOCKS, 256>>>(We[0], nullptr, 1, prelu, 1);

    // layer 1 (H=2, prelu)
    k_fold<<<16, 256>>>(Wq[1], bq[1], We[1], 2);
    k_node_gemm5<<<592, 320>>>(nullptr, 1, Wq[1], bq[1], Wk[1], bk[1], Wv[1], bv[1], Ws[1], bs[1]);
    k_edge_agg<2><<<EDGE_BLOCKS, 256>>>(We[1], nullptr, 1, prelu, 1);

    // layer 2 (H=1, no prelu, write d_out)
    k_fold<<<16, 256>>>(Wq[2], bq[2], We[2], 1);
    k_node_gemm5<<<592, 320>>>(nullptr, 1, Wq[2], bq[2], Wk[2], bk[2], Wv[2], bv[2], Ws[2], bs[2]);
    k_edge_agg<1><<<EDGE_BLOCKS, 256>>>(We[2], out, 0, prelu, 0);
}